// round 15
// baseline (speedup 1.0000x reference)
#include <cuda_runtime.h>
#include <cuda_fp16.h>
#include <math.h>
#include <float.h>
#include <stdint.h>

#define Tt 64
#define Bb 64
#define Ee 128
#define Hh 256
#define G4 1024
#define ND 20000
#define NI 50000
#define NSPLIT 14
#define DSPLIT 1429
#define KNT 12
#define CAP 64
#define EPSF 2.6e-3f
#define XWCTAS 380

// ---------------- scratch (device globals; no allocations) ----------------
__device__ float g_WihX[Ee*G4];
__device__ float g_WhhX[Hh*G4];
__device__ float g_bias4[G4];
__device__ float g_WqT[Hh*Hh];
__device__ float g_WkT[Hh*Hh];
__device__ float g_WvT[Hh*Hh];
__device__ float g_WoutT[Hh*Ee];
__device__ float g_dn[ND*Ee];
__device__ unsigned short g_dh1[ND*Ee];   // fp16 hi, PAIR-PERMUTED word order per row
__device__ float g_embs[Tt*Bb*Ee];
__device__ float g_qn[Tt*Bb*Ee];
__device__ float g_xw[Tt*Bb*G4];
__device__ float g_hbuf[2][Bb*Hh];
__device__ unsigned g_ctr;
__device__ unsigned g_xwdone;
__device__ float g_lstm[Bb*Tt*Hh];
__device__ float g_q[Bb*Tt*Hh];
__device__ float g_k[Bb*Tt*Hh];
__device__ float g_v[Bb*Tt*Hh];
__device__ float g_ctx[Bb*Hh];
__device__ float g_ao[Bb*Ee];
__device__ int   g_cand[Tt*Bb*NSPLIT*CAP];
__device__ float g_pbest[Tt*Bb*16];
__device__ int   g_pidx[Tt*Bb*16];
__device__ float g_fvec[Bb*Ee];

__device__ __forceinline__ uint32_t smem_u32(const void* p){
  uint32_t a;
  asm("{ .reg .u64 t; cvta.to.shared.u64 t, %1; cvt.u32.u64 %0, t; }" : "=r"(a) : "l"(p));
  return a;
}
__device__ __forceinline__ uint32_t fenc(float f){
  uint32_t u = __float_as_uint(f);
  return (u & 0x80000000u) ? ~u : (u | 0x80000000u);
}
__device__ __forceinline__ float fdec(uint32_t e){
  uint32_t u = (e & 0x80000000u) ? (e & 0x7fffffffu) : ~e;
  return __uint_as_float(u);
}

#define MMA16816(d, a, b0, b1) \
  asm volatile("mma.sync.aligned.m16n8k16.row.col.f32.f16.f16.f32 " \
    "{%0,%1,%2,%3}, {%4,%5,%6,%7}, {%8,%9}, {%0,%1,%2,%3};" \
    : "+f"((d)[0]),"+f"((d)[1]),"+f"((d)[2]),"+f"((d)[3]) \
    : "r"((a)[0]),"r"((a)[1]),"r"((a)[2]),"r"((a)[3]), "r"(b0),"r"(b1))

// ---------------- prep + data-embedding normalize (merged) ----------------
__global__ void prep_kernel(const float* __restrict__ Wih, const float* __restrict__ Whh,
                            const float* __restrict__ bih, const float* __restrict__ bhh,
                            const float* __restrict__ Wq, const float* __restrict__ Wk,
                            const float* __restrict__ Wv, const float* __restrict__ Wout,
                            const float* __restrict__ de){
  int tid = threadIdx.x;
  int i = blockIdx.x*blockDim.x + tid;
  if (i < Ee*G4){ int k=i>>10, n=i&1023, hh=n>>2, g=n&3; g_WihX[i] = Wih[(g*Hh+hh)*Ee + k]; }
  if (i < Hh*G4){ int hh=i>>10, r=i&1023, k=r>>2, g=r&3; g_WhhX[i] = Whh[(g*Hh+hh)*Hh + k]; }
  if (i < Hh*Hh){ int k=i/Hh, j=i%Hh; g_WqT[i]=Wq[j*Hh+k]; g_WkT[i]=Wk[j*Hh+k]; g_WvT[i]=Wv[j*Hh+k]; }
  if (i < Hh*Ee){ int h=i/Ee, e=i%Ee; g_WoutT[i] = Wout[e*Hh+h]; }
  if (i < G4){ int hh=i>>2, g=i&3; g_bias4[i] = bih[g*Hh+hh] + bhh[g*Hh+hh]; }
  if (i == 0){ g_ctr = 0u; g_xwdone = 0u; }
  if (i < Bb*Hh) g_hbuf[0][i] = 0.f;

  int row = blockIdx.x*2 + (tid>>7);
  __shared__ float red[8];
  if (row < ND){
    int e = tid & 127;
    float v = de[(size_t)row*Ee + e];
    float ss = v*v;
    #pragma unroll
    for (int off=16; off; off>>=1) ss += __shfl_xor_sync(0xffffffffu, ss, off);
    int wid = tid>>5;
    if ((tid&31)==0) red[wid] = ss;
    __syncthreads();
    int rb = (tid>>7)*4;
    float tot = red[rb]+red[rb+1]+red[rb+2]+red[rb+3];
    float nrm = fmaxf(sqrtf(tot), 1e-8f);
    float y = v / nrm;
    size_t gi = (size_t)row*Ee + e;
    g_dn[gi] = y;
    // pair-permuted fp16 word layout: word w = e>>1 (e even pairs handled by both lanes;
    // each thread writes one fp16 element into the permuted slot)
    int w = e >> 1;                // original word 0..63
    int c8 = w >> 3;               // chunk
    int r8 = w & 7;                // 0..7
    int wp = (r8 < 4) ? (c8*8 + r8*2) : (c8*8 + (r8-4)*2 + 1);
    g_dh1[(size_t)row*Ee + wp*2 + (e&1)] = __half_as_ushort(__float2half_rn(y));
  }
}

// ---------------- gather + positional enc + query normalize ----------------
__global__ void gather_kernel(const int* __restrict__ x, const float* __restrict__ emb){
  int qidx = blockIdx.x;
  int e = threadIdx.x;
  int b = qidx & 63;
  int xi = x[qidx];
  float v = emb[(size_t)xi*Ee + e];
  float ss = v*v;
  #pragma unroll
  for (int off=16; off; off>>=1) ss += __shfl_xor_sync(0xffffffffu, ss, off);
  __shared__ float red[4];
  if ((e&31)==0) red[e>>5] = ss;
  __syncthreads();
  float tot = red[0]+red[1]+red[2]+red[3];
  float nrm = fmaxf(sqrtf(tot), 1e-8f);
  g_qn[qidx*Ee + e] = v / nrm;
  float di  = expf(-logf(10000.0f) * (float)(2*(e>>1)) / (float)Ee);
  float ang = (float)b * di;
  g_embs[qidx*Ee + e] = v + ((e & 1) ? cosf(ang) : sinf(ang));
}

// ---------------- xw tile (device helper; tile tt of 1024: 64x64 block) ----------------
__device__ void xw_tile(int tt, float* sbuf, int tid){
  float (*sA)[65] = (float(*)[65])sbuf;
  float (*sB)[65] = (float(*)[65])(sbuf + 32*65);
  int n0 = (tt & 15)*64, m0 = (tt >> 4)*64;
  int tm=tid>>4, tn=tid&15;
  float acc[4][4] = {};
  for (int kc=0;kc<Ee;kc+=32){
    __syncthreads();
    for (int i=tid;i<64*32;i+=256){ int mm=i>>5,kk=i&31; sA[kk][mm] = g_embs[(m0+mm)*Ee + kc+kk]; }
    for (int i=tid;i<32*64;i+=256){ int kk=i>>6,nn=i&63; sB[kk][nn] = g_WihX[(kc+kk)*G4 + n0+nn]; }
    __syncthreads();
    for (int kk=0;kk<32;kk++){
      float av[4], bvv[4];
      #pragma unroll
      for (int im=0;im<4;im++)  av[im]  = sA[kk][tm+im*16];
      #pragma unroll
      for (int in_=0;in_<4;in_++) bvv[in_] = sB[kk][tn+in_*16];
      #pragma unroll
      for (int im=0;im<4;im++)
        #pragma unroll
        for (int in_=0;in_<4;in_++) acc[im][in_] += av[im]*bvv[in_];
    }
  }
  #pragma unroll
  for (int im=0;im<4;im++)
    #pragma unroll
    for (int in_=0;in_<4;in_++){
      int m=m0+tm+im*16, n=n0+tn+in_*16;
      g_xw[m*G4+n] = acc[im][in_] + g_bias4[n];
    }
}

// ---------------- kNN staging helper ----------------
#define BW 68
#define WPB (128*BW)

__device__ __forceinline__ void knn_stage(uint32_t* smw, int it, int dbeg, int dend, int tid){
  uint32_t* dst = smw + (it&1)*WPB;
  int dc = dbeg + it*128;
  for (int task=tid; task<2048; task+=256){
    int r=task>>4, u=task&15;
    int d=dc+r;
    uint32_t w = (uint32_t)(r*BW + 4*u);
    if (d<dend){
      const char* s1 = (const char*)g_dh1 + ((size_t)d*256 + 16*u);
      uint32_t a1 = smem_u32(dst + w);
      asm volatile("cp.async.ca.shared.global [%0], [%1], 16;" :: "r"(a1), "l"(s1) : "memory");
    } else {
      uint4 z = make_uint4(0,0,0,0);
      *(uint4*)(dst+w)=z;
    }
  }
  asm volatile("cp.async.commit_group;" ::: "memory");
}

// ---------------- FUSED: LSTM (blocks 0..63) + kNN (blocks 64..959, first 380 also do xw) ----------------
__global__ void __launch_bounds__(256,3) fused_lstm_knn_kernel(const int* __restrict__ lengths){
  extern __shared__ unsigned char smraw[];
  int tid = threadIdx.x;

  if (blockIdx.x < 64){
    // ================= LSTM role: 32 batches x 8 hidden units per CTA =================
    float* sm = (float*)smraw;
    float4* sW = (float4*)sm;                 // [8][256] float4
    float*  sH = sm + 8192;                   // [32][260]
    int bhalf = blockIdx.x >> 5;
    int octet = blockIdx.x & 31;
    int hu0 = octet*8;
    int bl  = tid & 31;
    int b   = bhalf*32 + bl;
    int hl  = tid >> 5;                       // 0..7
    int hh  = hu0 + hl;
    const float4* Wx = (const float4*)g_WhhX;
    for (int i=tid;i<2048;i+=256){
      int lhu=i>>8, k=i&255;
      sW[i] = Wx[(size_t)(hu0+lhu)*256 + k];
    }
    int mylen = lengths[b];
    float c = 0.f;
    const float4* xw4 = (const float4*)g_xw;
    unsigned* ctrp = &g_ctr;
    unsigned* xwdp = &g_xwdone;
    // wait for xw tiles (produced by kNN CTAs)
    if (tid == 0){
      unsigned cur;
      do {
        asm volatile("ld.acquire.gpu.global.u32 %0, [%1];" : "=r"(cur) : "l"(xwdp) : "memory");
      } while (cur < 1024u);
    }
    __syncthreads();
    for (int t=0;t<Tt;t++){
      const float4* hb4 = (const float4*)g_hbuf[t&1];
      for (int i=tid;i<2048;i+=256){
        int bb=i>>6, k4=i&63;
        float4 hv = __ldcg(hb4 + (bhalf*32+bb)*64 + k4);
        *(float4*)(sH + bb*260 + k4*4) = hv;
      }
      __syncthreads();
      float4 xv = __ldcg(&xw4[(size_t)(t*Bb+b)*Hh + hh]);   // prefetch under the dot
      float a0=0.f,a1=0.f,a2=0.f,a3=0.f;
      const float4* hrow4 = (const float4*)(sH + bl*260);
      const float4* wrow  = sW + hl*256;
      #pragma unroll 4
      for (int k4=0;k4<64;k4++){
        float4 hv = hrow4[k4];
        float4 w0 = wrow[4*k4+0];
        float4 w1 = wrow[4*k4+1];
        float4 w2 = wrow[4*k4+2];
        float4 w3 = wrow[4*k4+3];
        a0 += hv.x*w0.x + hv.y*w1.x + hv.z*w2.x + hv.w*w3.x;
        a1 += hv.x*w0.y + hv.y*w1.y + hv.z*w2.y + hv.w*w3.y;
        a2 += hv.x*w0.z + hv.y*w1.z + hv.z*w2.z + hv.w*w3.z;
        a3 += hv.x*w0.w + hv.y*w1.w + hv.z*w2.w + hv.w*w3.w;
      }
      a0 += xv.x; a1 += xv.y; a2 += xv.z; a3 += xv.w;
      float ig = 1.f/(1.f+expf(-a0));
      float fg = 1.f/(1.f+expf(-a1));
      float gg = tanhf(a2);
      float og = 1.f/(1.f+expf(-a3));
      c = fg*c + ig*gg;
      float hn = og * tanhf(c);
      __stcg(&g_hbuf[(t+1)&1][b*Hh+hh], hn);
      g_lstm[(b*Tt + t)*Hh + hh] = (t < mylen) ? hn : 0.f;
      __syncthreads();
      if (tid == 0){
        asm volatile("red.release.gpu.global.add.u32 [%0], 1;" :: "l"(ctrp) : "memory");
        unsigned tgt = (unsigned)(t+1)*64u, cur;
        do {
          asm volatile("ld.acquire.gpu.global.u32 %0, [%1];" : "=r"(cur) : "l"(ctrp) : "memory");
        } while (cur < tgt);
      }
      __syncthreads();
    }
  } else {
    // ================= kNN role (first XWCTAS blocks also produce xw tiles) =================
    uint32_t* smw = (uint32_t*)smraw;        // [2][WPB]
    __shared__ uint32_t runmax[64];
    __shared__ int scnt[64];
    int kb = blockIdx.x - 64;                 // 0..895

    if (kb < XWCTAS){
      unsigned* xwdp = &g_xwdone;
      for (int tt = kb; tt < 1024; tt += XWCTAS){
        xw_tile(tt, (float*)smraw, tid);
        __syncthreads();
        if (tid == 0)
          asm volatile("red.release.gpu.global.add.u32 [%0], 1;" :: "l"(xwdp) : "memory");
        __syncthreads();
      }
    }

    const int q0    = (kb & 63)*64;
    const int split = kb >> 6;                // 0..13
    const int dbeg  = split*DSPLIT;
    const int dend  = min(ND, dbeg+DSPLIT);
    int warp=tid>>5, lane=tid&31;
    int g=lane>>2, t4=lane&3;
    int wm=warp&3, wn=warp>>2;
    int r0 = wm*16+g, r1 = r0+8;

    if (tid < 64){ runmax[tid] = fenc(-FLT_MAX); scnt[tid] = 0; }

    uint32_t A1[8][4];
    {
      const float* base = g_qn + (size_t)(q0 + r0)*Ee;
      #pragma unroll
      for (int c=0;c<8;c++){
        #pragma unroll
        for (int p=0;p<4;p++){
          const float* rr = base + ((p&1)?8*Ee:0);
          int k = 16*c + 2*t4 + ((p&2)?8:0);
          __half h0=__float2half_rn(rr[k]), h1=__float2half_rn(rr[k+1]);
          A1[c][p] = (uint32_t)__half_as_ushort(h0) | ((uint32_t)__half_as_ushort(h1)<<16);
        }
      }
    }
    __syncthreads();

    knn_stage(smw, 0, dbeg, dend, tid);
    for (int it=0; it<KNT; it++){
      if (it+1<KNT){
        knn_stage(smw, it+1, dbeg, dend, tid);
        asm volatile("cp.async.wait_group 1;" ::: "memory");
      } else {
        asm volatile("cp.async.wait_group 0;" ::: "memory");
      }
      __syncthreads();
      const uint32_t* sB = smw + (it&1)*WPB;
      int dc = dbeg + it*128;

      float acc[8][4];
      #pragma unroll
      for (int nf=0;nf<8;nf++){ acc[nf][0]=0.f;acc[nf][1]=0.f;acc[nf][2]=0.f;acc[nf][3]=0.f; }
      #pragma unroll
      for (int c=0;c<8;c++){
        #pragma unroll
        for (int nf=0;nf<8;nf++){
          // pair-permuted layout: {b0,b1} adjacent -> one 8B load
          int basei = (wn*64 + nf*8 + g)*BW + 8*c + 2*t4;
          uint2 bb = *(const uint2*)(sB + basei);
          MMA16816(acc[nf], A1[c], bb.x, bb.y);
        }
      }

      float m0=-FLT_MAX, m1=-FLT_MAX;
      #pragma unroll
      for (int nf=0;nf<8;nf++){
        int d = dc + wn*64 + nf*8 + 2*t4;
        if (d   < dend){ m0=fmaxf(m0,acc[nf][0]); m1=fmaxf(m1,acc[nf][2]); }
        if (d+1 < dend){ m0=fmaxf(m0,acc[nf][1]); m1=fmaxf(m1,acc[nf][3]); }
      }
      if (m0 > -FLT_MAX) atomicMax(&runmax[r0], fenc(m0));
      if (m1 > -FLT_MAX) atomicMax(&runmax[r1], fenc(m1));
      __syncthreads();

      float thr0 = fdec(runmax[r0]) - EPSF;
      float thr1 = fdec(runmax[r1]) - EPSF;
      #pragma unroll
      for (int nf=0;nf<8;nf++){
        int d = dc + wn*64 + nf*8 + 2*t4;
        #pragma unroll
        for (int u=0;u<2;u++){
          if (d+u < dend){
            if (acc[nf][u] >= thr0){
              int slot = atomicAdd(&scnt[r0], 1);
              if (slot < CAP) g_cand[((size_t)(q0+r0)*NSPLIT + split)*CAP + slot] = d+u;
            }
            if (acc[nf][2+u] >= thr1){
              int slot = atomicAdd(&scnt[r1], 1);
              if (slot < CAP) g_cand[((size_t)(q0+r1)*NSPLIT + split)*CAP + slot] = d+u;
            }
          }
        }
      }
      __syncthreads();
    }

    // in-CTA exact fp32 rescore
    for (int qi = warp*8; qi < warp*8+8; qi++){
      int q = q0 + qi;
      int cnt = min(scnt[qi], CAP);
      const int* cl = g_cand + ((size_t)q*NSPLIT + split)*CAP;
      float4 qv = ((const float4*)(g_qn + (size_t)q*Ee))[lane];
      float bv = -FLT_MAX; int bi = 0x7fffffff;
      for (int j=0;j<cnt;j++){
        int d = cl[j];
        float4 dv = ((const float4*)(g_dn + (size_t)d*Ee))[lane];
        float s = qv.x*dv.x + qv.y*dv.y + qv.z*dv.z + qv.w*dv.w;
        #pragma unroll
        for (int off=16; off; off>>=1) s += __shfl_xor_sync(0xffffffffu, s, off);
        if (s > bv || (s == bv && d < bi)){ bv = s; bi = d; }
      }
      if (lane==0){
        g_pbest[q*16 + split] = bv;
        g_pidx [q*16 + split] = bi;
      }
    }
  }
}

// ---------------- q/k/v GEMMs ----------------
__global__ void qkv_kernel(const float* __restrict__ bq, const float* __restrict__ bk,
                           const float* __restrict__ bv){
  const float* WT   = (blockIdx.z==0)? g_WqT : (blockIdx.z==1)? g_WkT : g_WvT;
  const float* bias = (blockIdx.z==0)? bq   : (blockIdx.z==1)? bk   : bv;
  float* outp       = (blockIdx.z==0)? g_q  : (blockIdx.z==1)? g_k  : g_v;
  int m0 = blockIdx.y*64, n0 = blockIdx.x*64;
  int tid=threadIdx.x, tm=tid>>4, tn=tid&15;
  __shared__ float sA[32][65];
  __shared__ float sB[32][65];
  float acc[4][4] = {};
  for (int kc=0;kc<Hh;kc+=32){
    __syncthreads();
    for (int i=tid;i<64*32;i+=256){ int mm=i>>5,kk=i&31; sA[kk][mm] = g_lstm[(m0+mm)*Hh + kc+kk]; }
    for (int i=tid;i<32*64;i+=256){ int kk=i>>6,nn=i&63; sB[kk][nn] = WT[(kc+kk)*Hh + n0+nn]; }
    __syncthreads();
    for (int kk=0;kk<32;kk++){
      float av[4], bvv[4];
      #pragma unroll
      for (int im=0;im<4;im++)  av[im]  = sA[kk][tm+im*16];
      #pragma unroll
      for (int in_=0;in_<4;in_++) bvv[in_] = sB[kk][tn+in_*16];
      #pragma unroll
      for (int im=0;im<4;im++)
        #pragma unroll
        for (int in_=0;in_<4;in_++) acc[im][in_] += av[im]*bvv[in_];
    }
  }
  #pragma unroll
  for (int im=0;im<4;im++)
    #pragma unroll
    for (int in_=0;in_<4;in_++){
      int m=m0+tm+im*16, n=n0+tn+in_*16;
      outp[m*Hh+n] = acc[im][in_] + bias[n];
    }
}

// ---------------- attention per batch ----------------
__global__ void attn_kernel(){
  int b = blockIdx.x;
  int tid = threadIdx.x;     // 256
  extern __shared__ float sm[];
  float* sk  = sm;                 // [64][260]
  float* ssc = sk  + 64*260;       // [64][68]
  float* spm = ssc + 64*68;        // [64]
  float* swb = spm + 64;           // [64]
  for (int i=tid;i<64*Hh;i+=256){ int s=i>>8, h=i&255; sk[s*260+h] = g_k[(b*Tt+s)*Hh + h]; }
  {
    int s = tid>>2, sub = tid&3;
    float sum=0.f;
    const float* row = g_lstm + (b*Tt+s)*Hh + sub*64;
    for (int h=0;h<64;h++) sum += row[h];
    sum += __shfl_xor_sync(0xffffffffu, sum, 1);
    sum += __shfl_xor_sync(0xffffffffu, sum, 2);
    if (sub==0) spm[s] = (sum != 0.f) ? 1.f : 0.f;
  }
  __syncthreads();
  int trow = tid>>2, scol0 = tid&3;
  float sc[16] = {};
  const float* qrow = g_q + (b*Tt+trow)*Hh;
  for (int k=0;k<Hh;k++){
    float qv = qrow[k];
    #pragma unroll
    for (int j=0;j<16;j++) sc[j] += qv * sk[(scol0+4*j)*260 + k];
  }
  #pragma unroll
  for (int j=0;j<16;j++){
    int s = scol0+4*j;
    float v = sc[j] * 0.0625f;
    if (spm[s]==0.f) v = -1e30f;
    sc[j] = v;
  }
  float mx=-1e30f;
  #pragma unroll
  for (int j=0;j<16;j++) mx = fmaxf(mx, sc[j]);
  mx = fmaxf(mx, __shfl_xor_sync(0xffffffffu, mx, 1));
  mx = fmaxf(mx, __shfl_xor_sync(0xffffffffu, mx, 2));
  float sum=0.f;
  #pragma unroll
  for (int j=0;j<16;j++){ sc[j]=expf(sc[j]-mx); sum+=sc[j]; }
  sum += __shfl_xor_sync(0xffffffffu, sum, 1);
  sum += __shfl_xor_sync(0xffffffffu, sum, 2);
  float inv = 1.f/sum;
  #pragma unroll
  for (int j=0;j<16;j++) ssc[trow*68 + scol0+4*j] = sc[j]*inv;
  __syncthreads();
  if (tid < 64){
    float w=0.f;
    for (int t2=0;t2<64;t2++) w += ssc[t2*68+tid];
    swb[tid] = w * (1.f/64.f);
  }
  __syncthreads();
  {
    int h = tid;
    float cx=0.f;
    for (int s=0;s<64;s++) cx += swb[s] * g_v[(b*Tt+s)*Hh + h];
    g_ctx[b*Hh+h] = cx;
  }
}

// ---------------- attn_output ----------------
__global__ void attnout_kernel(const float* __restrict__ bout){
  int b = blockIdx.x, e = threadIdx.x;
  __shared__ float sc[Hh];
  for (int i=e;i<Hh;i+=128) sc[i]=g_ctx[b*Hh+i];
  __syncthreads();
  float acc = bout[e];
  for (int h=0;h<Hh;h++) acc += sc[h]*g_WoutT[h*Ee+e];
  g_ao[b*Ee+e] = acc;
}

// ---------------- closest: NSPLIT-way argmax + gather + attn_output multiply ----------------
__global__ void closest_kernel(const float* __restrict__ de){
  int b = blockIdx.x, tid = threadIdx.x;   // 128 threads
  __shared__ int sidx[64];
  if (tid < 64){
    int q = tid*64 + b;
    float bv=-FLT_MAX; int bi=0x7fffffff;
    #pragma unroll
    for (int s=0;s<NSPLIT;s++){
      float v = g_pbest[q*16+s]; int id = g_pidx[q*16+s];
      if (v>bv || (v==bv && id<bi)){ bv=v; bi=id; }
    }
    sidx[tid] = bi;
  }
  __syncthreads();
  float s = 0.f;
  for (int t2=0;t2<Tt;t2++) s += de[(size_t)sidx[t2]*Ee + tid];
  g_fvec[b*Ee+tid] = g_ao[b*Ee+tid] * (s * (1.f/64.f));
}

// ---------------- final: out(64,50000) = fvec @ emb_table^T ----------------
__global__ void __launch_bounds__(256) final_kernel(const float* __restrict__ emb,
                                                    float* __restrict__ out){
  __shared__ float4 sf4[Bb*32];
  int tid = threadIdx.x;
  for (int i=tid;i<Bb*32;i+=256) sf4[i]=((const float4*)g_fvec)[i];
  __syncthreads();
  int n = blockIdx.x*256 + tid;
  if (n >= NI) return;
  float acc[64];
  #pragma unroll
  for (int b=0;b<64;b++) acc[b]=0.f;
  const float4* er = reinterpret_cast<const float4*>(emb + (size_t)n*Ee);
  for (int kk=0;kk<32;kk++){
    float4 ev = er[kk];
    #pragma unroll
    for (int b=0;b<64;b++){
      float4 f = sf4[b*32+kk];
      acc[b] += f.x*ev.x + f.y*ev.y + f.z*ev.z + f.w*ev.w;
    }
  }
  #pragma unroll 4
  for (int b=0;b<64;b++) out[(size_t)b*NI + n] = acc[b];
}

// ---------------- launch ----------------
extern "C" void kernel_launch(void* const* d_in, const int* in_sizes, int n_in,
                              void* d_out, int out_size){
  const int*   x    = (const int*)  d_in[0];
  const int*   len  = (const int*)  d_in[1];
  const float* emb  = (const float*)d_in[2];
  const float* de   = (const float*)d_in[3];
  const float* Wih  = (const float*)d_in[4];
  const float* Whh  = (const float*)d_in[5];
  const float* bih  = (const float*)d_in[6];
  const float* bhh  = (const float*)d_in[7];
  const float* Wq   = (const float*)d_in[8];
  const float* bq   = (const float*)d_in[9];
  const float* Wk   = (const float*)d_in[10];
  const float* bk   = (const float*)d_in[11];
  const float* Wv   = (const float*)d_in[12];
  const float* bv   = (const float*)d_in[13];
  const float* Wout = (const float*)d_in[14];
  const float* bout = (const float*)d_in[15];
  float* out = (float*)d_out;

  static const int FUSED_SMEM = 2*WPB*4;   // 69632 B -> 3 CTAs/SM
  cudaFuncSetAttribute(fused_lstm_knn_kernel, cudaFuncAttributeMaxDynamicSharedMemorySize, FUSED_SMEM);
  cudaFuncSetAttribute(attn_kernel, cudaFuncAttributeMaxDynamicSharedMemorySize, 21120*4);

  prep_kernel<<<10000,256>>>(Wih,Whh,bih,bhh,Wq,Wk,Wv,Wout,de);    // 1
  gather_kernel<<<Tt*Bb,128>>>(x, emb);                             // 2
  fused_lstm_knn_kernel<<<64 + 64*NSPLIT, 256, FUSED_SMEM>>>(len);  // 3 <-- xw folded in
  dim3 gq(4,64,3);
  qkv_kernel<<<gq,256>>>(bq,bk,bv);                                 // 4
  attn_kernel<<<Bb,256, 21120*4>>>();                               // 5
  attnout_kernel<<<Bb,128>>>(bout);                                 // 6
  closest_kernel<<<Bb,128>>>(de);                                   // 7
  final_kernel<<<(NI+255)/256,256>>>(emb, out);                     // 8
}

// round 16
// speedup vs baseline: 1.0051x; 1.0051x over previous
#include <cuda_runtime.h>
#include <cuda_fp16.h>
#include <math.h>
#include <float.h>
#include <stdint.h>

#define Tt 64
#define Bb 64
#define Ee 128
#define Hh 256
#define G4 1024
#define ND 20000
#define NI 50000
#define NSPLIT 14
#define DSPLIT 1429
#define KNT 12
#define CAP 64
#define EPSF 2.6e-3f

// ---------------- scratch (device globals; no allocations) ----------------
__device__ float g_WihX[Ee*G4];
__device__ float g_WhhX[Hh*G4];
__device__ float g_bias4[G4];
__device__ float g_WqT[Hh*Hh];
__device__ float g_WkT[Hh*Hh];
__device__ float g_WvT[Hh*Hh];
__device__ float g_WoutT[Hh*Ee];
__device__ float g_dn[ND*Ee];
__device__ unsigned short g_dh1[ND*Ee];   // fp16 hi, PAIR-PERMUTED word order per row
__device__ float g_embs[Tt*Bb*Ee];
__device__ float g_qn[Tt*Bb*Ee];
__device__ float g_xw[Tt*Bb*G4];
__device__ float g_hbuf[2][Bb*Hh];
__device__ unsigned g_ctr;
__device__ float g_lstm[Bb*Tt*Hh];
__device__ float g_q[Bb*Tt*Hh];
__device__ float g_k[Bb*Tt*Hh];
__device__ float g_v[Bb*Tt*Hh];
__device__ float g_ctx[Bb*Hh];
__device__ float g_ao[Bb*Ee];
__device__ int   g_cand[Tt*Bb*NSPLIT*CAP];
__device__ float g_pbest[Tt*Bb*16];
__device__ int   g_pidx[Tt*Bb*16];
__device__ float g_fvec[Bb*Ee];

__device__ __forceinline__ uint32_t smem_u32(const void* p){
  uint32_t a;
  asm("{ .reg .u64 t; cvta.to.shared.u64 t, %1; cvt.u32.u64 %0, t; }" : "=r"(a) : "l"(p));
  return a;
}
__device__ __forceinline__ uint32_t fenc(float f){
  uint32_t u = __float_as_uint(f);
  return (u & 0x80000000u) ? ~u : (u | 0x80000000u);
}
__device__ __forceinline__ float fdec(uint32_t e){
  uint32_t u = (e & 0x80000000u) ? (e & 0x7fffffffu) : ~e;
  return __uint_as_float(u);
}

#define MMA16816(d, a, b0, b1) \
  asm volatile("mma.sync.aligned.m16n8k16.row.col.f32.f16.f16.f32 " \
    "{%0,%1,%2,%3}, {%4,%5,%6,%7}, {%8,%9}, {%0,%1,%2,%3};" \
    : "+f"((d)[0]),"+f"((d)[1]),"+f"((d)[2]),"+f"((d)[3]) \
    : "r"((a)[0]),"r"((a)[1]),"r"((a)[2]),"r"((a)[3]), "r"(b0),"r"(b1))

// ---------------- prep + data-embedding normalize (merged) ----------------
__global__ void prep_kernel(const float* __restrict__ Wih, const float* __restrict__ Whh,
                            const float* __restrict__ bih, const float* __restrict__ bhh,
                            const float* __restrict__ Wq, const float* __restrict__ Wk,
                            const float* __restrict__ Wv, const float* __restrict__ Wout,
                            const float* __restrict__ de){
  int tid = threadIdx.x;
  int i = blockIdx.x*blockDim.x + tid;
  if (i < Ee*G4){ int k=i>>10, n=i&1023, hh=n>>2, g=n&3; g_WihX[i] = Wih[(g*Hh+hh)*Ee + k]; }
  if (i < Hh*G4){ int hh=i>>10, r=i&1023, k=r>>2, g=r&3; g_WhhX[i] = Whh[(g*Hh+hh)*Hh + k]; }
  if (i < Hh*Hh){ int k=i/Hh, j=i%Hh; g_WqT[i]=Wq[j*Hh+k]; g_WkT[i]=Wk[j*Hh+k]; g_WvT[i]=Wv[j*Hh+k]; }
  if (i < Hh*Ee){ int h=i/Ee, e=i%Ee; g_WoutT[i] = Wout[e*Hh+h]; }
  if (i < G4){ int hh=i>>2, g=i&3; g_bias4[i] = bih[g*Hh+hh] + bhh[g*Hh+hh]; }
  if (i == 0) g_ctr = 0u;
  if (i < Bb*Hh) g_hbuf[0][i] = 0.f;

  int row = blockIdx.x*2 + (tid>>7);
  __shared__ float red[8];
  if (row < ND){
    int e = tid & 127;
    float v = de[(size_t)row*Ee + e];
    float ss = v*v;
    #pragma unroll
    for (int off=16; off; off>>=1) ss += __shfl_xor_sync(0xffffffffu, ss, off);
    int wid = tid>>5;
    if ((tid&31)==0) red[wid] = ss;
    __syncthreads();
    int rb = (tid>>7)*4;
    float tot = red[rb]+red[rb+1]+red[rb+2]+red[rb+3];
    float nrm = fmaxf(sqrtf(tot), 1e-8f);
    float y = v / nrm;
    size_t gi = (size_t)row*Ee + e;
    g_dn[gi] = y;
    // pair-permuted fp16 word layout: original word w -> slot wp so that the
    // kNN lane's {b0,b1} (words 8c+t4, 8c+4+t4) are adjacent (one LDS.64).
    int w = e >> 1;
    int c8 = w >> 3;
    int r8 = w & 7;
    int wp = (r8 < 4) ? (c8*8 + r8*2) : (c8*8 + (r8-4)*2 + 1);
    g_dh1[(size_t)row*Ee + wp*2 + (e&1)] = __half_as_ushort(__float2half_rn(y));
  }
}

// ---------------- gather + positional enc + query normalize ----------------
__global__ void gather_kernel(const int* __restrict__ x, const float* __restrict__ emb){
  int qidx = blockIdx.x;
  int e = threadIdx.x;
  int b = qidx & 63;
  int xi = x[qidx];
  float v = emb[(size_t)xi*Ee + e];
  float ss = v*v;
  #pragma unroll
  for (int off=16; off; off>>=1) ss += __shfl_xor_sync(0xffffffffu, ss, off);
  __shared__ float red[4];
  if ((e&31)==0) red[e>>5] = ss;
  __syncthreads();
  float tot = red[0]+red[1]+red[2]+red[3];
  float nrm = fmaxf(sqrtf(tot), 1e-8f);
  g_qn[qidx*Ee + e] = v / nrm;
  float di  = expf(-logf(10000.0f) * (float)(2*(e>>1)) / (float)Ee);
  float ang = (float)b * di;
  g_embs[qidx*Ee + e] = v + ((e & 1) ? cosf(ang) : sinf(ang));
}

// ---------------- xw = embs @ WihX + bias4 ----------------
__global__ void xw_kernel(){
  int m0 = blockIdx.y*64, n0 = blockIdx.x*64;
  int tid=threadIdx.x, tm=tid>>4, tn=tid&15;
  __shared__ float sA[32][65];
  __shared__ float sB[32][65];
  float acc[4][4] = {};
  for (int kc=0;kc<Ee;kc+=32){
    __syncthreads();
    for (int i=tid;i<64*32;i+=256){ int mm=i>>5,kk=i&31; sA[kk][mm] = g_embs[(m0+mm)*Ee + kc+kk]; }
    for (int i=tid;i<32*64;i+=256){ int kk=i>>6,nn=i&63; sB[kk][nn] = g_WihX[(kc+kk)*G4 + n0+nn]; }
    __syncthreads();
    for (int kk=0;kk<32;kk++){
      float av[4], bvv[4];
      #pragma unroll
      for (int im=0;im<4;im++)  av[im]  = sA[kk][tm+im*16];
      #pragma unroll
      for (int in_=0;in_<4;in_++) bvv[in_] = sB[kk][tn+in_*16];
      #pragma unroll
      for (int im=0;im<4;im++)
        #pragma unroll
        for (int in_=0;in_<4;in_++) acc[im][in_] += av[im]*bvv[in_];
    }
  }
  #pragma unroll
  for (int im=0;im<4;im++)
    #pragma unroll
    for (int in_=0;in_<4;in_++){
      int m=m0+tm+im*16, n=n0+tn+in_*16;
      g_xw[m*G4+n] = acc[im][in_] + g_bias4[n];
    }
}

// ---------------- kNN staging helper ----------------
#define BW 68
#define WPB (128*BW)

__device__ __forceinline__ void knn_stage(uint32_t* smw, int it, int dbeg, int dend, int tid){
  uint32_t* dst = smw + (it&1)*WPB;
  int dc = dbeg + it*128;
  for (int task=tid; task<2048; task+=256){
    int r=task>>4, u=task&15;
    int d=dc+r;
    uint32_t w = (uint32_t)(r*BW + 4*u);
    if (d<dend){
      const char* s1 = (const char*)g_dh1 + ((size_t)d*256 + 16*u);
      uint32_t a1 = smem_u32(dst + w);
      asm volatile("cp.async.ca.shared.global [%0], [%1], 16;" :: "r"(a1), "l"(s1) : "memory");
    } else {
      uint4 z = make_uint4(0,0,0,0);
      *(uint4*)(dst+w)=z;
    }
  }
  asm volatile("cp.async.commit_group;" ::: "memory");
}

// ---------------- FUSED: LSTM first (blocks 0..63), kNN (blocks 64..959) ----------------
__global__ void __launch_bounds__(256,3) fused_lstm_knn_kernel(const int* __restrict__ lengths){
  extern __shared__ unsigned char smraw[];
  int tid = threadIdx.x;

  if (blockIdx.x < 64){
    // ================= LSTM role: 32 batches x 8 hidden units per CTA =================
    float* sm = (float*)smraw;
    float4* sW = (float4*)sm;                 // [8][256] float4
    float*  sH = sm + 8192;                   // [32][260]
    int bhalf = blockIdx.x >> 5;
    int octet = blockIdx.x & 31;
    int hu0 = octet*8;
    int bl  = tid & 31;
    int b   = bhalf*32 + bl;
    int hl  = tid >> 5;                       // 0..7
    int hh  = hu0 + hl;
    const float4* Wx = (const float4*)g_WhhX;
    for (int i=tid;i<2048;i+=256){
      int lhu=i>>8, k=i&255;
      sW[i] = Wx[(size_t)(hu0+lhu)*256 + k];
    }
    int mylen = lengths[b];
    float c = 0.f;
    const float4* xw4 = (const float4*)g_xw;
    unsigned* ctrp = &g_ctr;
    for (int t=0;t<Tt;t++){
      const float4* hb4 = (const float4*)g_hbuf[t&1];
      for (int i=tid;i<2048;i+=256){
        int bb=i>>6, k4=i&63;
        float4 hv = __ldcg(hb4 + (bhalf*32+bb)*64 + k4);
        *(float4*)(sH + bb*260 + k4*4) = hv;
      }
      __syncthreads();
      float4 xv = __ldcg(&xw4[(size_t)(t*Bb+b)*Hh + hh]);   // prefetch under the dot
      float a0=0.f,a1=0.f,a2=0.f,a3=0.f;
      const float4* hrow4 = (const float4*)(sH + bl*260);
      const float4* wrow  = sW + hl*256;
      #pragma unroll 4
      for (int k4=0;k4<64;k4++){
        float4 hv = hrow4[k4];
        float4 w0 = wrow[4*k4+0];
        float4 w1 = wrow[4*k4+1];
        float4 w2 = wrow[4*k4+2];
        float4 w3 = wrow[4*k4+3];
        a0 += hv.x*w0.x + hv.y*w1.x + hv.z*w2.x + hv.w*w3.x;
        a1 += hv.x*w0.y + hv.y*w1.y + hv.z*w2.y + hv.w*w3.y;
        a2 += hv.x*w0.z + hv.y*w1.z + hv.z*w2.z + hv.w*w3.z;
        a3 += hv.x*w0.w + hv.y*w1.w + hv.z*w2.w + hv.w*w3.w;
      }
      a0 += xv.x; a1 += xv.y; a2 += xv.z; a3 += xv.w;
      float ig = 1.f/(1.f+expf(-a0));
      float fg = 1.f/(1.f+expf(-a1));
      float gg = tanhf(a2);
      float og = 1.f/(1.f+expf(-a3));
      c = fg*c + ig*gg;
      float hn = og * tanhf(c);
      __stcg(&g_hbuf[(t+1)&1][b*Hh+hh], hn);
      g_lstm[(b*Tt + t)*Hh + hh] = (t < mylen) ? hn : 0.f;
      __syncthreads();                      // CTA stores ordered before tid0's release
      if (tid == 0){
        asm volatile("red.release.gpu.global.add.u32 [%0], 1;" :: "l"(ctrp) : "memory");
        unsigned tgt = (unsigned)(t+1)*64u, cur;
        do {
          asm volatile("ld.acquire.gpu.global.u32 %0, [%1];" : "=r"(cur) : "l"(ctrp) : "memory");
        } while (cur < tgt);
      }
      __syncthreads();
    }
  } else {
    // ================= kNN filter + in-CTA exact rescore =================
    uint32_t* smw = (uint32_t*)smraw;        // [2][WPB]
    __shared__ uint32_t runmax[64];
    __shared__ int scnt[64];
    int kb = blockIdx.x - 64;                 // 0..895
    const int q0    = (kb & 63)*64;
    const int split = kb >> 6;                // 0..13
    const int dbeg  = split*DSPLIT;
    const int dend  = min(ND, dbeg+DSPLIT);
    int warp=tid>>5, lane=tid&31;
    int g=lane>>2, t4=lane&3;
    int wm=warp&3, wn=warp>>2;
    int r0 = wm*16+g, r1 = r0+8;

    if (tid < 64){ runmax[tid] = fenc(-FLT_MAX); scnt[tid] = 0; }

    uint32_t A1[8][4];
    {
      const float* base = g_qn + (size_t)(q0 + r0)*Ee;
      #pragma unroll
      for (int c=0;c<8;c++){
        #pragma unroll
        for (int p=0;p<4;p++){
          const float* rr = base + ((p&1)?8*Ee:0);
          int k = 16*c + 2*t4 + ((p&2)?8:0);
          __half h0=__float2half_rn(rr[k]), h1=__float2half_rn(rr[k+1]);
          A1[c][p] = (uint32_t)__half_as_ushort(h0) | ((uint32_t)__half_as_ushort(h1)<<16);
        }
      }
    }

    knn_stage(smw, 0, dbeg, dend, tid);
    for (int it=0; it<KNT; it++){
      if (it+1<KNT){
        knn_stage(smw, it+1, dbeg, dend, tid);
        asm volatile("cp.async.wait_group 1;" ::: "memory");
      } else {
        asm volatile("cp.async.wait_group 0;" ::: "memory");
      }
      __syncthreads();
      const uint32_t* sB = smw + (it&1)*WPB;
      int dc = dbeg + it*128;

      float acc[8][4];
      #pragma unroll
      for (int nf=0;nf<8;nf++){ acc[nf][0]=0.f;acc[nf][1]=0.f;acc[nf][2]=0.f;acc[nf][3]=0.f; }
      #pragma unroll
      for (int c=0;c<8;c++){
        #pragma unroll
        for (int nf=0;nf<8;nf++){
          // pair-permuted layout: {b0,b1} adjacent -> one LDS.64
          int basei = (wn*64 + nf*8 + g)*BW + 8*c + 2*t4;
          uint2 bb = *(const uint2*)(sB + basei);
          MMA16816(acc[nf], A1[c], bb.x, bb.y);
        }
      }

      float m0=-FLT_MAX, m1=-FLT_MAX;
      #pragma unroll
      for (int nf=0;nf<8;nf++){
        int d = dc + wn*64 + nf*8 + 2*t4;
        if (d   < dend){ m0=fmaxf(m0,acc[nf][0]); m1=fmaxf(m1,acc[nf][2]); }
        if (d+1 < dend){ m0=fmaxf(m0,acc[nf][1]); m1=fmaxf(m1,acc[nf][3]); }
      }
      if (m0 > -FLT_MAX) atomicMax(&runmax[r0], fenc(m0));
      if (m1 > -FLT_MAX) atomicMax(&runmax[r1], fenc(m1));
      __syncthreads();

      float thr0 = fdec(runmax[r0]) - EPSF;
      float thr1 = fdec(runmax[r1]) - EPSF;
      #pragma unroll
      for (int nf=0;nf<8;nf++){
        int d = dc + wn*64 + nf*8 + 2*t4;
        #pragma unroll
        for (int u=0;u<2;u++){
          if (d+u < dend){
            if (acc[nf][u] >= thr0){
              int slot = atomicAdd(&scnt[r0], 1);
              if (slot < CAP) g_cand[((size_t)(q0+r0)*NSPLIT + split)*CAP + slot] = d+u;
            }
            if (acc[nf][2+u] >= thr1){
              int slot = atomicAdd(&scnt[r1], 1);
              if (slot < CAP) g_cand[((size_t)(q0+r1)*NSPLIT + split)*CAP + slot] = d+u;
            }
          }
        }
      }
      __syncthreads();
    }

    // in-CTA exact fp32 rescore
    for (int qi = warp*8; qi < warp*8+8; qi++){
      int q = q0 + qi;
      int cnt = min(scnt[qi], CAP);
      const int* cl = g_cand + ((size_t)q*NSPLIT + split)*CAP;
      float4 qv = ((const float4*)(g_qn + (size_t)q*Ee))[lane];
      float bv = -FLT_MAX; int bi = 0x7fffffff;
      for (int j=0;j<cnt;j++){
        int d = cl[j];
        float4 dv = ((const float4*)(g_dn + (size_t)d*Ee))[lane];
        float s = qv.x*dv.x + qv.y*dv.y + qv.z*dv.z + qv.w*dv.w;
        #pragma unroll
        for (int off=16; off; off>>=1) s += __shfl_xor_sync(0xffffffffu, s, off);
        if (s > bv || (s == bv && d < bi)){ bv = s; bi = d; }
      }
      if (lane==0){
        g_pbest[q*16 + split] = bv;
        g_pidx [q*16 + split] = bi;
      }
    }
  }
}

// ---------------- q/k/v GEMMs ----------------
__global__ void qkv_kernel(const float* __restrict__ bq, const float* __restrict__ bk,
                           const float* __restrict__ bv){
  const float* WT   = (blockIdx.z==0)? g_WqT : (blockIdx.z==1)? g_WkT : g_WvT;
  const float* bias = (blockIdx.z==0)? bq   : (blockIdx.z==1)? bk   : bv;
  float* outp       = (blockIdx.z==0)? g_q  : (blockIdx.z==1)? g_k  : g_v;
  int m0 = blockIdx.y*64, n0 = blockIdx.x*64;
  int tid=threadIdx.x, tm=tid>>4, tn=tid&15;
  __shared__ float sA[32][65];
  __shared__ float sB[32][65];
  float acc[4][4] = {};
  for (int kc=0;kc<Hh;kc+=32){
    __syncthreads();
    for (int i=tid;i<64*32;i+=256){ int mm=i>>5,kk=i&31; sA[kk][mm] = g_lstm[(m0+mm)*Hh + kc+kk]; }
    for (int i=tid;i<32*64;i+=256){ int kk=i>>6,nn=i&63; sB[kk][nn] = WT[(kc+kk)*Hh + n0+nn]; }
    __syncthreads();
    for (int kk=0;kk<32;kk++){
      float av[4], bvv[4];
      #pragma unroll
      for (int im=0;im<4;im++)  av[im]  = sA[kk][tm+im*16];
      #pragma unroll
      for (int in_=0;in_<4;in_++) bvv[in_] = sB[kk][tn+in_*16];
      #pragma unroll
      for (int im=0;im<4;im++)
        #pragma unroll
        for (int in_=0;in_<4;in_++) acc[im][in_] += av[im]*bvv[in_];
    }
  }
  #pragma unroll
  for (int im=0;im<4;im++)
    #pragma unroll
    for (int in_=0;in_<4;in_++){
      int m=m0+tm+im*16, n=n0+tn+in_*16;
      outp[m*Hh+n] = acc[im][in_] + bias[n];
    }
}

// ---------------- attention per batch ----------------
__global__ void attn_kernel(){
  int b = blockIdx.x;
  int tid = threadIdx.x;     // 256
  extern __shared__ float sm[];
  float* sk  = sm;                 // [64][260]
  float* ssc = sk  + 64*260;       // [64][68]
  float* spm = ssc + 64*68;        // [64]
  float* swb = spm + 64;           // [64]
  for (int i=tid;i<64*Hh;i+=256){ int s=i>>8, h=i&255; sk[s*260+h] = g_k[(b*Tt+s)*Hh + h]; }
  {
    int s = tid>>2, sub = tid&3;
    float sum=0.f;
    const float* row = g_lstm + (b*Tt+s)*Hh + sub*64;
    for (int h=0;h<64;h++) sum += row[h];
    sum += __shfl_xor_sync(0xffffffffu, sum, 1);
    sum += __shfl_xor_sync(0xffffffffu, sum, 2);
    if (sub==0) spm[s] = (sum != 0.f) ? 1.f : 0.f;
  }
  __syncthreads();
  int trow = tid>>2, scol0 = tid&3;
  float sc[16] = {};
  const float* qrow = g_q + (b*Tt+trow)*Hh;
  for (int k=0;k<Hh;k++){
    float qv = qrow[k];
    #pragma unroll
    for (int j=0;j<16;j++) sc[j] += qv * sk[(scol0+4*j)*260 + k];
  }
  #pragma unroll
  for (int j=0;j<16;j++){
    int s = scol0+4*j;
    float v = sc[j] * 0.0625f;
    if (spm[s]==0.f) v = -1e30f;
    sc[j] = v;
  }
  float mx=-1e30f;
  #pragma unroll
  for (int j=0;j<16;j++) mx = fmaxf(mx, sc[j]);
  mx = fmaxf(mx, __shfl_xor_sync(0xffffffffu, mx, 1));
  mx = fmaxf(mx, __shfl_xor_sync(0xffffffffu, mx, 2));
  float sum=0.f;
  #pragma unroll
  for (int j=0;j<16;j++){ sc[j]=expf(sc[j]-mx); sum+=sc[j]; }
  sum += __shfl_xor_sync(0xffffffffu, sum, 1);
  sum += __shfl_xor_sync(0xffffffffu, sum, 2);
  float inv = 1.f/sum;
  #pragma unroll
  for (int j=0;j<16;j++) ssc[trow*68 + scol0+4*j] = sc[j]*inv;
  __syncthreads();
  if (tid < 64){
    float w=0.f;
    for (int t2=0;t2<64;t2++) w += ssc[t2*68+tid];
    swb[tid] = w * (1.f/64.f);
  }
  __syncthreads();
  {
    int h = tid;
    float cx=0.f;
    for (int s=0;s<64;s++) cx += swb[s] * g_v[(b*Tt+s)*Hh + h];
    g_ctx[b*Hh+h] = cx;
  }
}

// ---------------- attn_output ----------------
__global__ void attnout_kernel(const float* __restrict__ bout){
  int b = blockIdx.x, e = threadIdx.x;
  __shared__ float sc[Hh];
  for (int i=e;i<Hh;i+=128) sc[i]=g_ctx[b*Hh+i];
  __syncthreads();
  float acc = bout[e];
  for (int h=0;h<Hh;h++) acc += sc[h]*g_WoutT[h*Ee+e];
  g_ao[b*Ee+e] = acc;
}

// ---------------- closest: NSPLIT-way argmax + gather + attn_output multiply ----------------
__global__ void closest_kernel(const float* __restrict__ de){
  int b = blockIdx.x, tid = threadIdx.x;   // 128 threads
  __shared__ int sidx[64];
  if (tid < 64){
    int q = tid*64 + b;
    float bv=-FLT_MAX; int bi=0x7fffffff;
    #pragma unroll
    for (int s=0;s<NSPLIT;s++){
      float v = g_pbest[q*16+s]; int id = g_pidx[q*16+s];
      if (v>bv || (v==bv && id<bi)){ bv=v; bi=id; }
    }
    sidx[tid] = bi;
  }
  __syncthreads();
  float s = 0.f;
  for (int t2=0;t2<Tt;t2++) s += de[(size_t)sidx[t2]*Ee + tid];
  g_fvec[b*Ee+tid] = g_ao[b*Ee+tid] * (s * (1.f/64.f));
}

// ---------------- final: out(64,50000) = fvec @ emb_table^T ----------------
__global__ void __launch_bounds__(256) final_kernel(const float* __restrict__ emb,
                                                    float* __restrict__ out){
  __shared__ float4 sf4[Bb*32];
  int tid = threadIdx.x;
  for (int i=tid;i<Bb*32;i+=256) sf4[i]=((const float4*)g_fvec)[i];
  __syncthreads();
  int n = blockIdx.x*256 + tid;
  if (n >= NI) return;
  float acc[64];
  #pragma unroll
  for (int b=0;b<64;b++) acc[b]=0.f;
  const float4* er = reinterpret_cast<const float4*>(emb + (size_t)n*Ee);
  for (int kk=0;kk<32;kk++){
    float4 ev = er[kk];
    #pragma unroll
    for (int b=0;b<64;b++){
      float4 f = sf4[b*32+kk];
      acc[b] += f.x*ev.x + f.y*ev.y + f.z*ev.z + f.w*ev.w;
    }
  }
  #pragma unroll 4
  for (int b=0;b<64;b++) out[(size_t)b*NI + n] = acc[b];
}

// ---------------- launch ----------------
extern "C" void kernel_launch(void* const* d_in, const int* in_sizes, int n_in,
                              void* d_out, int out_size){
  const int*   x    = (const int*)  d_in[0];
  const int*   len  = (const int*)  d_in[1];
  const float* emb  = (const float*)d_in[2];
  const float* de   = (const float*)d_in[3];
  const float* Wih  = (const float*)d_in[4];
  const float* Whh  = (const float*)d_in[5];
  const float* bih  = (const float*)d_in[6];
  const float* bhh  = (const float*)d_in[7];
  const float* Wq   = (const float*)d_in[8];
  const float* bq   = (const float*)d_in[9];
  const float* Wk   = (const float*)d_in[10];
  const float* bk   = (const float*)d_in[11];
  const float* Wv   = (const float*)d_in[12];
  const float* bv   = (const float*)d_in[13];
  const float* Wout = (const float*)d_in[14];
  const float* bout = (const float*)d_in[15];
  float* out = (float*)d_out;

  static const int FUSED_SMEM = 2*WPB*4;   // 69632 B -> 3 CTAs/SM
  cudaFuncSetAttribute(fused_lstm_knn_kernel, cudaFuncAttributeMaxDynamicSharedMemorySize, FUSED_SMEM);
  cudaFuncSetAttribute(attn_kernel, cudaFuncAttributeMaxDynamicSharedMemorySize, 21120*4);

  prep_kernel<<<10000,256>>>(Wih,Whh,bih,bhh,Wq,Wk,Wv,Wout,de);    // 1
  gather_kernel<<<Tt*Bb,128>>>(x, emb);                             // 2
  dim3 gx(16,64);
  xw_kernel<<<gx,256>>>();                                          // 3
  fused_lstm_knn_kernel<<<64 + 64*NSPLIT, 256, FUSED_SMEM>>>(len);  // 4 <-- profiled
  dim3 gq(4,64,3);
  qkv_kernel<<<gq,256>>>(bq,bk,bv);                                 // 5
  attn_kernel<<<Bb,256, 21120*4>>>();                               // 6
  attnout_kernel<<<Bb,128>>>(bout);                                 // 7
  closest_kernel<<<Bb,128>>>(de);                                   // 8
  final_kernel<<<(NI+255)/256,256>>>(emb, out);                     // 9
}

// round 17
// speedup vs baseline: 1.0476x; 1.0423x over previous
#include <cuda_runtime.h>
#include <cuda_fp16.h>
#include <math.h>
#include <float.h>
#include <stdint.h>

#define Tt 64
#define Bb 64
#define Ee 128
#define Hh 256
#define G4 1024
#define ND 20000
#define NI 50000
#define NSPLIT 14
#define DSPLIT 1429
#define KNT 12
#define CAP 64
#define EPSF 2.6e-3f

// ---------------- scratch (device globals; no allocations) ----------------
__device__ float g_WihX[Ee*G4];
__device__ float g_WhhX[Hh*G4];
__device__ float g_bias4[G4];
__device__ float g_WqT[Hh*Hh];
__device__ float g_WkT[Hh*Hh];
__device__ float g_WvT[Hh*Hh];
__device__ float g_WoutT[Hh*Ee];
__device__ float g_dn[ND*Ee];
__device__ unsigned short g_dh1[ND*Ee];   // fp16 hi of normalized data emb
__device__ float g_embs[Tt*Bb*Ee];
__device__ float g_qn[Tt*Bb*Ee];
__device__ float g_xw[Tt*Bb*G4];
__device__ float g_hbuf[2][Bb*Hh];
__device__ unsigned g_ctr;
__device__ float g_lstm[Bb*Tt*Hh];
__device__ float g_q[Bb*Tt*Hh];
__device__ float g_k[Bb*Tt*Hh];
__device__ float g_v[Bb*Tt*Hh];
__device__ float g_ao[Bb*Ee];
__device__ int   g_cand[Tt*Bb*NSPLIT*CAP];
__device__ float g_pbest[Tt*Bb*16];
__device__ int   g_pidx[Tt*Bb*16];
__device__ float g_fvec[Bb*Ee];

__device__ __forceinline__ uint32_t smem_u32(const void* p){
  uint32_t a;
  asm("{ .reg .u64 t; cvta.to.shared.u64 t, %1; cvt.u32.u64 %0, t; }" : "=r"(a) : "l"(p));
  return a;
}
__device__ __forceinline__ uint32_t fenc(float f){
  uint32_t u = __float_as_uint(f);
  return (u & 0x80000000u) ? ~u : (u | 0x80000000u);
}
__device__ __forceinline__ float fdec(uint32_t e){
  uint32_t u = (e & 0x80000000u) ? (e & 0x7fffffffu) : ~e;
  return __uint_as_float(u);
}

#define MMA16816(d, a, b0, b1) \
  asm volatile("mma.sync.aligned.m16n8k16.row.col.f32.f16.f16.f32 " \
    "{%0,%1,%2,%3}, {%4,%5,%6,%7}, {%8,%9}, {%0,%1,%2,%3};" \
    : "+f"((d)[0]),"+f"((d)[1]),"+f"((d)[2]),"+f"((d)[3]) \
    : "r"((a)[0]),"r"((a)[1]),"r"((a)[2]),"r"((a)[3]), "r"(b0),"r"(b1))

// ---------------- prep + data-embedding normalize (merged) ----------------
__global__ void prep_kernel(const float* __restrict__ Wih, const float* __restrict__ Whh,
                            const float* __restrict__ bih, const float* __restrict__ bhh,
                            const float* __restrict__ Wq, const float* __restrict__ Wk,
                            const float* __restrict__ Wv, const float* __restrict__ Wout,
                            const float* __restrict__ de){
  int tid = threadIdx.x;
  int i = blockIdx.x*blockDim.x + tid;
  if (i < Ee*G4){ int k=i>>10, n=i&1023, hh=n>>2, g=n&3; g_WihX[i] = Wih[(g*Hh+hh)*Ee + k]; }
  if (i < Hh*G4){ int hh=i>>10, r=i&1023, k=r>>2, g=r&3; g_WhhX[i] = Whh[(g*Hh+hh)*Hh + k]; }
  if (i < Hh*Hh){ int k=i/Hh, j=i%Hh; g_WqT[i]=Wq[j*Hh+k]; g_WkT[i]=Wk[j*Hh+k]; g_WvT[i]=Wv[j*Hh+k]; }
  if (i < Hh*Ee){ int h=i/Ee, e=i%Ee; g_WoutT[i] = Wout[e*Hh+h]; }
  if (i < G4){ int hh=i>>2, g=i&3; g_bias4[i] = bih[g*Hh+hh] + bhh[g*Hh+hh]; }
  if (i == 0) g_ctr = 0u;
  if (i < Bb*Hh) g_hbuf[0][i] = 0.f;

  int row = blockIdx.x*2 + (tid>>7);
  __shared__ float red[8];
  if (row < ND){
    int e = tid & 127;
    float v = de[(size_t)row*Ee + e];
    float ss = v*v;
    #pragma unroll
    for (int off=16; off; off>>=1) ss += __shfl_xor_sync(0xffffffffu, ss, off);
    int wid = tid>>5;
    if ((tid&31)==0) red[wid] = ss;
    __syncthreads();
    int rb = (tid>>7)*4;
    float tot = red[rb]+red[rb+1]+red[rb+2]+red[rb+3];
    float nrm = fmaxf(sqrtf(tot), 1e-8f);
    float y = v / nrm;
    size_t gi = (size_t)row*Ee + e;
    g_dn[gi] = y;
    g_dh1[gi] = __half_as_ushort(__float2half_rn(y));
  }
}

// ---------------- gather + positional enc + query normalize ----------------
__global__ void gather_kernel(const int* __restrict__ x, const float* __restrict__ emb){
  int qidx = blockIdx.x;
  int e = threadIdx.x;
  int b = qidx & 63;
  int xi = x[qidx];
  float v = emb[(size_t)xi*Ee + e];
  float ss = v*v;
  #pragma unroll
  for (int off=16; off; off>>=1) ss += __shfl_xor_sync(0xffffffffu, ss, off);
  __shared__ float red[4];
  if ((e&31)==0) red[e>>5] = ss;
  __syncthreads();
  float tot = red[0]+red[1]+red[2]+red[3];
  float nrm = fmaxf(sqrtf(tot), 1e-8f);
  g_qn[qidx*Ee + e] = v / nrm;
  float di  = expf(-logf(10000.0f) * (float)(2*(e>>1)) / (float)Ee);
  float ang = (float)b * di;
  g_embs[qidx*Ee + e] = v + ((e & 1) ? cosf(ang) : sinf(ang));
}

// ---------------- xw = embs @ WihX + bias4 ----------------
__global__ void xw_kernel(){
  int m0 = blockIdx.y*64, n0 = blockIdx.x*64;
  int tid=threadIdx.x, tm=tid>>4, tn=tid&15;
  __shared__ float sA[32][65];
  __shared__ float sB[32][65];
  float acc[4][4] = {};
  for (int kc=0;kc<Ee;kc+=32){
    __syncthreads();
    for (int i=tid;i<64*32;i+=256){ int mm=i>>5,kk=i&31; sA[kk][mm] = g_embs[(m0+mm)*Ee + kc+kk]; }
    for (int i=tid;i<32*64;i+=256){ int kk=i>>6,nn=i&63; sB[kk][nn] = g_WihX[(kc+kk)*G4 + n0+nn]; }
    __syncthreads();
    for (int kk=0;kk<32;kk++){
      float av[4], bvv[4];
      #pragma unroll
      for (int im=0;im<4;im++)  av[im]  = sA[kk][tm+im*16];
      #pragma unroll
      for (int in_=0;in_<4;in_++) bvv[in_] = sB[kk][tn+in_*16];
      #pragma unroll
      for (int im=0;im<4;im++)
        #pragma unroll
        for (int in_=0;in_<4;in_++) acc[im][in_] += av[im]*bvv[in_];
    }
  }
  #pragma unroll
  for (int im=0;im<4;im++)
    #pragma unroll
    for (int in_=0;in_<4;in_++){
      int m=m0+tm+im*16, n=n0+tn+in_*16;
      g_xw[m*G4+n] = acc[im][in_] + g_bias4[n];
    }
}

// ---------------- kNN staging helper ----------------
#define BW 68
#define WPB (128*BW)

__device__ __forceinline__ void knn_stage(uint32_t* smw, int it, int dbeg, int dend, int tid){
  uint32_t* dst = smw + (it&1)*WPB;
  int dc = dbeg + it*128;
  for (int task=tid; task<2048; task+=256){
    int r=task>>4, u=task&15;
    int d=dc+r;
    uint32_t w = (uint32_t)(r*BW + 4*u);
    if (d<dend){
      const char* s1 = (const char*)g_dh1 + ((size_t)d*256 + 16*u);
      uint32_t a1 = smem_u32(dst + w);
      asm volatile("cp.async.ca.shared.global [%0], [%1], 16;" :: "r"(a1), "l"(s1) : "memory");
    } else {
      uint4 z = make_uint4(0,0,0,0);
      *(uint4*)(dst+w)=z;
    }
  }
  asm volatile("cp.async.commit_group;" ::: "memory");
}

// ---------------- FUSED: LSTM first (blocks 0..63), kNN (blocks 64..959) ----------------
__global__ void __launch_bounds__(256,3) fused_lstm_knn_kernel(const int* __restrict__ lengths){
  extern __shared__ unsigned char smraw[];
  int tid = threadIdx.x;

  if (blockIdx.x < 64){
    // ================= LSTM role: 32 batches x 8 hidden units per CTA =================
    float* sm = (float*)smraw;
    float4* sW = (float4*)sm;                 // [8][256] float4
    float*  sH = sm + 8192;                   // [32][260]
    int bhalf = blockIdx.x >> 5;
    int octet = blockIdx.x & 31;
    int hu0 = octet*8;
    int bl  = tid & 31;
    int b   = bhalf*32 + bl;
    int hl  = tid >> 5;                       // 0..7
    int hh  = hu0 + hl;
    const float4* Wx = (const float4*)g_WhhX;
    for (int i=tid;i<2048;i+=256){
      int lhu=i>>8, k=i&255;
      sW[i] = Wx[(size_t)(hu0+lhu)*256 + k];
    }
    int mylen = lengths[b];
    float c = 0.f;
    const float4* xw4 = (const float4*)g_xw;
    unsigned* ctrp = &g_ctr;
    for (int t=0;t<Tt;t++){
      const float4* hb4 = (const float4*)g_hbuf[t&1];
      for (int i=tid;i<2048;i+=256){
        int bb=i>>6, k4=i&63;
        float4 hv = __ldcg(hb4 + (bhalf*32+bb)*64 + k4);
        *(float4*)(sH + bb*260 + k4*4) = hv;
      }
      __syncthreads();
      float4 xv = __ldcg(&xw4[(size_t)(t*Bb+b)*Hh + hh]);   // prefetch under the dot
      float a0=0.f,a1=0.f,a2=0.f,a3=0.f;
      const float4* hrow4 = (const float4*)(sH + bl*260);
      const float4* wrow  = sW + hl*256;
      #pragma unroll 4
      for (int k4=0;k4<64;k4++){
        float4 hv = hrow4[k4];
        float4 w0 = wrow[4*k4+0];
        float4 w1 = wrow[4*k4+1];
        float4 w2 = wrow[4*k4+2];
        float4 w3 = wrow[4*k4+3];
        a0 += hv.x*w0.x + hv.y*w1.x + hv.z*w2.x + hv.w*w3.x;
        a1 += hv.x*w0.y + hv.y*w1.y + hv.z*w2.y + hv.w*w3.y;
        a2 += hv.x*w0.z + hv.y*w1.z + hv.z*w2.z + hv.w*w3.z;
        a3 += hv.x*w0.w + hv.y*w1.w + hv.z*w2.w + hv.w*w3.w;
      }
      a0 += xv.x; a1 += xv.y; a2 += xv.z; a3 += xv.w;
      float ig = 1.f/(1.f+expf(-a0));
      float fg = 1.f/(1.f+expf(-a1));
      float gg = tanhf(a2);
      float og = 1.f/(1.f+expf(-a3));
      c = fg*c + ig*gg;
      float hn = og * tanhf(c);
      __stcg(&g_hbuf[(t+1)&1][b*Hh+hh], hn);
      g_lstm[(b*Tt + t)*Hh + hh] = (t < mylen) ? hn : 0.f;
      __syncthreads();                      // CTA stores ordered before tid0's release
      if (tid == 0){
        asm volatile("red.release.gpu.global.add.u32 [%0], 1;" :: "l"(ctrp) : "memory");
        unsigned tgt = (unsigned)(t+1)*64u, cur;
        do {
          asm volatile("ld.acquire.gpu.global.u32 %0, [%1];" : "=r"(cur) : "l"(ctrp) : "memory");
        } while (cur < tgt);
      }
      __syncthreads();
    }
  } else {
    // ================= kNN filter + in-CTA exact rescore =================
    uint32_t* smw = (uint32_t*)smraw;        // [2][WPB]
    __shared__ uint32_t runmax[64];
    __shared__ int scnt[64];
    int kb = blockIdx.x - 64;                 // 0..895
    const int q0    = (kb & 63)*64;
    const int split = kb >> 6;                // 0..13
    const int dbeg  = split*DSPLIT;
    const int dend  = min(ND, dbeg+DSPLIT);
    int warp=tid>>5, lane=tid&31;
    int g=lane>>2, t4=lane&3;
    int wm=warp&3, wn=warp>>2;
    int r0 = wm*16+g, r1 = r0+8;

    if (tid < 64){ runmax[tid] = fenc(-FLT_MAX); scnt[tid] = 0; }

    uint32_t A1[8][4];
    {
      const float* base = g_qn + (size_t)(q0 + r0)*Ee;
      #pragma unroll
      for (int c=0;c<8;c++){
        #pragma unroll
        for (int p=0;p<4;p++){
          const float* rr = base + ((p&1)?8*Ee:0);
          int k = 16*c + 2*t4 + ((p&2)?8:0);
          __half h0=__float2half_rn(rr[k]), h1=__float2half_rn(rr[k+1]);
          A1[c][p] = (uint32_t)__half_as_ushort(h0) | ((uint32_t)__half_as_ushort(h1)<<16);
        }
      }
    }

    knn_stage(smw, 0, dbeg, dend, tid);
    for (int it=0; it<KNT; it++){
      if (it+1<KNT){
        knn_stage(smw, it+1, dbeg, dend, tid);
        asm volatile("cp.async.wait_group 1;" ::: "memory");
      } else {
        asm volatile("cp.async.wait_group 0;" ::: "memory");
      }
      __syncthreads();
      const uint32_t* sB = smw + (it&1)*WPB;
      int dc = dbeg + it*128;

      float acc[8][4];
      #pragma unroll
      for (int nf=0;nf<8;nf++){ acc[nf][0]=0.f;acc[nf][1]=0.f;acc[nf][2]=0.f;acc[nf][3]=0.f; }
      #pragma unroll
      for (int c=0;c<8;c++){
        #pragma unroll
        for (int nf=0;nf<8;nf++){
          int basei = (wn*64 + nf*8 + g)*BW + 8*c + t4;
          uint32_t b0=sB[basei], b1=sB[basei+4];
          MMA16816(acc[nf], A1[c], b0, b1);
        }
      }

      float m0=-FLT_MAX, m1=-FLT_MAX;
      #pragma unroll
      for (int nf=0;nf<8;nf++){
        int d = dc + wn*64 + nf*8 + 2*t4;
        if (d   < dend){ m0=fmaxf(m0,acc[nf][0]); m1=fmaxf(m1,acc[nf][2]); }
        if (d+1 < dend){ m0=fmaxf(m0,acc[nf][1]); m1=fmaxf(m1,acc[nf][3]); }
      }
      if (m0 > -FLT_MAX) atomicMax(&runmax[r0], fenc(m0));
      if (m1 > -FLT_MAX) atomicMax(&runmax[r1], fenc(m1));
      __syncthreads();

      float thr0 = fdec(runmax[r0]) - EPSF;
      float thr1 = fdec(runmax[r1]) - EPSF;
      #pragma unroll
      for (int nf=0;nf<8;nf++){
        int d = dc + wn*64 + nf*8 + 2*t4;
        #pragma unroll
        for (int u=0;u<2;u++){
          if (d+u < dend){
            if (acc[nf][u] >= thr0){
              int slot = atomicAdd(&scnt[r0], 1);
              if (slot < CAP) g_cand[((size_t)(q0+r0)*NSPLIT + split)*CAP + slot] = d+u;
            }
            if (acc[nf][2+u] >= thr1){
              int slot = atomicAdd(&scnt[r1], 1);
              if (slot < CAP) g_cand[((size_t)(q0+r1)*NSPLIT + split)*CAP + slot] = d+u;
            }
          }
        }
      }
      __syncthreads();
    }

    // in-CTA exact fp32 rescore
    for (int qi = warp*8; qi < warp*8+8; qi++){
      int q = q0 + qi;
      int cnt = min(scnt[qi], CAP);
      const int* cl = g_cand + ((size_t)q*NSPLIT + split)*CAP;
      float4 qv = ((const float4*)(g_qn + (size_t)q*Ee))[lane];
      float bv = -FLT_MAX; int bi = 0x7fffffff;
      for (int j=0;j<cnt;j++){
        int d = cl[j];
        float4 dv = ((const float4*)(g_dn + (size_t)d*Ee))[lane];
        float s = qv.x*dv.x + qv.y*dv.y + qv.z*dv.z + qv.w*dv.w;
        #pragma unroll
        for (int off=16; off; off>>=1) s += __shfl_xor_sync(0xffffffffu, s, off);
        if (s > bv || (s == bv && d < bi)){ bv = s; bi = d; }
      }
      if (lane==0){
        g_pbest[q*16 + split] = bv;
        g_pidx [q*16 + split] = bi;
      }
    }
  }
}

// ---------------- q/k/v GEMMs ----------------
__global__ void qkv_kernel(const float* __restrict__ bq, const float* __restrict__ bk,
                           const float* __restrict__ bv){
  const float* WT   = (blockIdx.z==0)? g_WqT : (blockIdx.z==1)? g_WkT : g_WvT;
  const float* bias = (blockIdx.z==0)? bq   : (blockIdx.z==1)? bk   : bv;
  float* outp       = (blockIdx.z==0)? g_q  : (blockIdx.z==1)? g_k  : g_v;
  int m0 = blockIdx.y*64, n0 = blockIdx.x*64;
  int tid=threadIdx.x, tm=tid>>4, tn=tid&15;
  __shared__ float sA[32][65];
  __shared__ float sB[32][65];
  float acc[4][4] = {};
  for (int kc=0;kc<Hh;kc+=32){
    __syncthreads();
    for (int i=tid;i<64*32;i+=256){ int mm=i>>5,kk=i&31; sA[kk][mm] = g_lstm[(m0+mm)*Hh + kc+kk]; }
    for (int i=tid;i<32*64;i+=256){ int kk=i>>6,nn=i&63; sB[kk][nn] = WT[(kc+kk)*Hh + n0+nn]; }
    __syncthreads();
    for (int kk=0;kk<32;kk++){
      float av[4], bvv[4];
      #pragma unroll
      for (int im=0;im<4;im++)  av[im]  = sA[kk][tm+im*16];
      #pragma unroll
      for (int in_=0;in_<4;in_++) bvv[in_] = sB[kk][tn+in_*16];
      #pragma unroll
      for (int im=0;im<4;im++)
        #pragma unroll
        for (int in_=0;in_<4;in_++) acc[im][in_] += av[im]*bvv[in_];
    }
  }
  #pragma unroll
  for (int im=0;im<4;im++)
    #pragma unroll
    for (int in_=0;in_<4;in_++){
      int m=m0+tm+im*16, n=n0+tn+in_*16;
      outp[m*Hh+n] = acc[im][in_] + bias[n];
    }
}

// ---------------- attention per batch (+ fused attn_output) ----------------
__global__ void attn_kernel(const float* __restrict__ bout){
  int b = blockIdx.x;
  int tid = threadIdx.x;     // 256
  extern __shared__ float sm[];
  float* sk  = sm;                 // [64][260]
  float* ssc = sk  + 64*260;       // [64][68]
  float* spm = ssc + 64*68;        // [64]
  float* swb = spm + 64;           // [64]
  float* sctx= swb + 64;           // [256]
  for (int i=tid;i<64*Hh;i+=256){ int s=i>>8, h=i&255; sk[s*260+h] = g_k[(b*Tt+s)*Hh + h]; }
  {
    int s = tid>>2, sub = tid&3;
    float sum=0.f;
    const float* row = g_lstm + (b*Tt+s)*Hh + sub*64;
    for (int h=0;h<64;h++) sum += row[h];
    sum += __shfl_xor_sync(0xffffffffu, sum, 1);
    sum += __shfl_xor_sync(0xffffffffu, sum, 2);
    if (sub==0) spm[s] = (sum != 0.f) ? 1.f : 0.f;
  }
  __syncthreads();
  int trow = tid>>2, scol0 = tid&3;
  float sc[16] = {};
  const float* qrow = g_q + (b*Tt+trow)*Hh;
  for (int k=0;k<Hh;k++){
    float qv = qrow[k];
    #pragma unroll
    for (int j=0;j<16;j++) sc[j] += qv * sk[(scol0+4*j)*260 + k];
  }
  #pragma unroll
  for (int j=0;j<16;j++){
    int s = scol0+4*j;
    float v = sc[j] * 0.0625f;
    if (spm[s]==0.f) v = -1e30f;
    sc[j] = v;
  }
  float mx=-1e30f;
  #pragma unroll
  for (int j=0;j<16;j++) mx = fmaxf(mx, sc[j]);
  mx = fmaxf(mx, __shfl_xor_sync(0xffffffffu, mx, 1));
  mx = fmaxf(mx, __shfl_xor_sync(0xffffffffu, mx, 2));
  float sum=0.f;
  #pragma unroll
  for (int j=0;j<16;j++){ sc[j]=expf(sc[j]-mx); sum+=sc[j]; }
  sum += __shfl_xor_sync(0xffffffffu, sum, 1);
  sum += __shfl_xor_sync(0xffffffffu, sum, 2);
  float inv = 1.f/sum;
  #pragma unroll
  for (int j=0;j<16;j++) ssc[trow*68 + scol0+4*j] = sc[j]*inv;
  __syncthreads();
  if (tid < 64){
    float w=0.f;
    for (int t2=0;t2<64;t2++) w += ssc[t2*68+tid];
    swb[tid] = w * (1.f/64.f);
  }
  __syncthreads();
  {
    int h = tid;
    float cx=0.f;
    for (int s=0;s<64;s++) cx += swb[s] * g_v[(b*Tt+s)*Hh + h];
    sctx[h] = cx;
  }
  __syncthreads();
  if (tid < Ee){
    int e = tid;
    float acc = bout[e];
    for (int h=0;h<Hh;h++) acc += sctx[h]*g_WoutT[h*Ee+e];
    g_ao[b*Ee+e] = acc;
  }
}

// ---------------- closest: NSPLIT-way argmax + gather + attn_output multiply ----------------
__global__ void closest_kernel(const float* __restrict__ de){
  int b = blockIdx.x, tid = threadIdx.x;   // 128 threads
  __shared__ int sidx[64];
  if (tid < 64){
    int q = tid*64 + b;
    float bv=-FLT_MAX; int bi=0x7fffffff;
    #pragma unroll
    for (int s=0;s<NSPLIT;s++){
      float v = g_pbest[q*16+s]; int id = g_pidx[q*16+s];
      if (v>bv || (v==bv && id<bi)){ bv=v; bi=id; }
    }
    sidx[tid] = bi;
  }
  __syncthreads();
  float s = 0.f;
  for (int t2=0;t2<Tt;t2++) s += de[(size_t)sidx[t2]*Ee + tid];
  g_fvec[b*Ee+tid] = g_ao[b*Ee+tid] * (s * (1.f/64.f));
}

// ---------------- final: out(64,50000) = fvec @ emb_table^T ----------------
__global__ void __launch_bounds__(256) final_kernel(const float* __restrict__ emb,
                                                    float* __restrict__ out){
  __shared__ float4 sf4[Bb*32];
  int tid = threadIdx.x;
  for (int i=tid;i<Bb*32;i+=256) sf4[i]=((const float4*)g_fvec)[i];
  __syncthreads();
  int n = blockIdx.x*256 + tid;
  if (n >= NI) return;
  float acc[64];
  #pragma unroll
  for (int b=0;b<64;b++) acc[b]=0.f;
  const float4* er = reinterpret_cast<const float4*>(emb + (size_t)n*Ee);
  for (int kk=0;kk<32;kk++){
    float4 ev = er[kk];
    #pragma unroll
    for (int b=0;b<64;b++){
      float4 f = sf4[b*32+kk];
      acc[b] += f.x*ev.x + f.y*ev.y + f.z*ev.z + f.w*ev.w;
    }
  }
  #pragma unroll 4
  for (int b=0;b<64;b++) out[(size_t)b*NI + n] = acc[b];
}

// ---------------- launch ----------------
extern "C" void kernel_launch(void* const* d_in, const int* in_sizes, int n_in,
                              void* d_out, int out_size){
  const int*   x    = (const int*)  d_in[0];
  const int*   len  = (const int*)  d_in[1];
  const float* emb  = (const float*)d_in[2];
  const float* de   = (const float*)d_in[3];
  const float* Wih  = (const float*)d_in[4];
  const float* Whh  = (const float*)d_in[5];
  const float* bih  = (const float*)d_in[6];
  const float* bhh  = (const float*)d_in[7];
  const float* Wq   = (const float*)d_in[8];
  const float* bq   = (const float*)d_in[9];
  const float* Wk   = (const float*)d_in[10];
  const float* bk   = (const float*)d_in[11];
  const float* Wv   = (const float*)d_in[12];
  const float* bv   = (const float*)d_in[13];
  const float* Wout = (const float*)d_in[14];
  const float* bout = (const float*)d_in[15];
  float* out = (float*)d_out;

  static const int FUSED_SMEM = 2*WPB*4;              // 69632 B -> 3 CTAs/SM
  static const int ATTN_SMEM  = (64*260 + 64*68 + 64 + 64 + 256) * 4;
  cudaFuncSetAttribute(fused_lstm_knn_kernel, cudaFuncAttributeMaxDynamicSharedMemorySize, FUSED_SMEM);
  cudaFuncSetAttribute(attn_kernel, cudaFuncAttributeMaxDynamicSharedMemorySize, ATTN_SMEM);

  prep_kernel<<<10000,256>>>(Wih,Whh,bih,bhh,Wq,Wk,Wv,Wout,de);    // 1
  gather_kernel<<<Tt*Bb,128>>>(x, emb);                             // 2
  dim3 gx(16,64);
  xw_kernel<<<gx,256>>>();                                          // 3
  fused_lstm_knn_kernel<<<64 + 64*NSPLIT, 256, FUSED_SMEM>>>(len);  // 4
  dim3 gq(4,64,3);
  qkv_kernel<<<gq,256>>>(bq,bk,bv);                                 // 5
  attn_kernel<<<Bb,256, ATTN_SMEM>>>(bout);                         // 6 (attn_output fused)
  closest_kernel<<<Bb,128>>>(de);                                   // 7
  final_kernel<<<(NI+255)/256,256>>>(emb, out);                     // 8
}